// round 14
// baseline (speedup 1.0000x reference)
#include <cuda_runtime.h>
#include <cuda_bf16.h>
#include <math.h>

#define T_STEPS 200
#define BATCH   128
#define HID     1024
#define K_IN    120
#define NOUT    12
#define BH      (BATCH*HID)      // 131072
#define NROWS   (T_STEPS*BATCH)  // 25600

// ---------------- static device scratch (no allocations allowed) ------------
__device__ float          g_F[NROWS*HID];       // W1 drive, then overwritten by D = S1@Wd^T
__device__ float          g_WrT[1025*HID];      // Wr^T fp32 [h][j] + zero pad row
__device__ __nv_bfloat16  g_WdB[3][HID*HID];    // Wd 3-way bf16 split, [j][h] native layout
__device__ __nv_bfloat16  g_W1B[3][HID*128];    // W1 3-way bf16 split, [n][k] padded 120->128
__device__ float          g_W2T[HID*NOUT];
__device__ unsigned       g_m1[(size_t)BATCH*T_STEPS*32];    // layer-1 spike masks (h-linear)
__device__ unsigned       g_masks[(size_t)BATCH*T_STEPS*32]; // recurrent spike ballots
__device__ float          g_ctab[T_STEPS*NOUT];
__device__ float          g_csum[NOUT];
__device__ int            g_done[T_STEPS];      // dgemm tile-completion counters

// ---------------- prep: Wr transpose, Wd/W1 3-split, W2T, tables, flags ------
__global__ __launch_bounds__(256)
void k_prep(const float* __restrict__ Wd, const float* __restrict__ Wr,
            const float* __restrict__ W1, const float* __restrict__ W2,
            const float* __restrict__ tau_m2) {
    int idx = blockIdx.x * 256 + threadIdx.x;
    if (idx < HID*HID) {
        int j = idx >> 10, h = idx & 1023;
        g_WrT[(size_t)h*HID + j] = Wr[idx];      // Wr^T[h][j]
        float w = Wd[idx];
        __nv_bfloat16 h1 = __float2bfloat16(w);
        float r1 = w - __bfloat162float(h1);
        __nv_bfloat16 h2 = __float2bfloat16(r1);
        float r2 = r1 - __bfloat162float(h2);
        __nv_bfloat16 h3 = __float2bfloat16(r2);
        g_WdB[0][idx] = h1;
        g_WdB[1][idx] = h2;
        g_WdB[2][idx] = h3;
    }
    if (idx < HID*128) {                         // W1 split, K padded to 128
        int n = idx >> 7, k = idx & 127;
        float w = (k < K_IN) ? W1[n*K_IN + k] : 0.0f;
        __nv_bfloat16 h1 = __float2bfloat16(w);
        float r1 = w - __bfloat162float(h1);
        __nv_bfloat16 h2 = __float2bfloat16(r1);
        float r2 = r1 - __bfloat162float(h2);
        __nv_bfloat16 h3 = __float2bfloat16(r2);
        g_W1B[0][idx] = h1;
        g_W1B[1][idx] = h2;
        g_W1B[2][idx] = h3;
    }
    if (idx < HID*NOUT) {
        int h = idx / NOUT, o = idx % NOUT;
        g_W2T[idx] = W2[o*HID + h];
    }
    if (idx < T_STEPS*NOUT) {
        int k = idx / NOUT, o = idx % NOUT;
        float a2 = expf(-1.0f / tau_m2[o]);
        g_ctab[idx] = 1.0f - powf(a2, (float)(T_STEPS - k));
    }
    if (idx < NOUT) {
        float a2 = expf(-1.0f / tau_m2[idx]);
        float s = 0.0f, p = 1.0f;
        for (int n = 1; n <= T_STEPS; n++) { p *= a2; s += p; }
        g_csum[idx] = (float)T_STEPS - s;
    }
    if (idx < HID) g_WrT[(size_t)1024*HID + idx] = 0.0f;   // zero pad row
    if (idx < T_STEPS) g_done[idx] = 0;                    // reset every launch
}

// ---------------- shared mma helpers ------------------------------------------
__device__ __forceinline__ void mma16816(float* c, const unsigned* a, unsigned b0, unsigned b1) {
    asm volatile("mma.sync.aligned.m16n8k16.row.col.f32.bf16.bf16.f32 "
        "{%0,%1,%2,%3}, {%4,%5,%6,%7}, {%8,%9}, {%0,%1,%2,%3};"
        : "+f"(c[0]), "+f"(c[1]), "+f"(c[2]), "+f"(c[3])
        : "r"(a[0]), "r"(a[1]), "r"(a[2]), "r"(a[3]), "r"(b0), "r"(b1));
}
__device__ __forceinline__ unsigned spike_pack(unsigned m, int c) {
    return (((m >> c) & 1u) ? 0x3F80u : 0u) | (((m >> (c+1)) & 1u) ? 0x3F800000u : 0u);
}
__device__ __forceinline__ void cp16(unsigned dst, const void* src) {
    asm volatile("cp.async.cg.shared.global [%0], [%1], 16;" :: "r"(dst), "l"(src) : "memory");
}
__device__ __forceinline__ float4 ldcg4(const float4* p) {
    float4 v;
    asm volatile("ld.global.cg.v4.f32 {%0,%1,%2,%3}, [%4];"
        : "=f"(v.x), "=f"(v.y), "=f"(v.z), "=f"(v.w) : "l"(p));
    return v;
}

// ---------------- K1: F = ternary(X) @ W1^T + b1 via mma (bf16 3-split) -------
__global__ __launch_bounds__(128, 3)
void k_in_mma(const float* __restrict__ X, const float* __restrict__ thrp,
              const float* __restrict__ b1) {
    __shared__ unsigned short As[128][40];
    __shared__ unsigned Bs[2][3][64][20];
    const int tid = threadIdx.x, lane = tid & 31, w = tid >> 5;
    const int wm = w & 1, wn = w >> 1;
    const int tt = blockIdx.x, Nb = blockIdx.y * 64;
    const int r = lane >> 2, t4 = lane & 3;
    const float thr = __ldg(thrp);
    float acc[4][4][4] = {};

    const uint4* w1b4 = (const uint4*)g_W1B;
    const unsigned sbB = (unsigned)__cvta_generic_to_shared(Bs);

    auto stageB = [&](int kc, int buf) {
        #pragma unroll
        for (int i = tid; i < 768; i += 128) {
            int s = i >> 8, rem = i & 255, n = rem >> 2, kq = rem & 3;
            unsigned dst = sbB + (unsigned)((((buf*3 + s)*64 + n)*20 + kq*4)*4);
            cp16(dst, w1b4 + (size_t)s*16384 + (size_t)(Nb + n)*16 + kc*4 + kq);
        }
        asm volatile("cp.async.commit_group;" ::: "memory");
    };
    stageB(0, 0);

    for (int kc = 0; kc < 4; kc++) {
        {
            int kk = kc*32 + lane;
            int c = kk / 40, f = kk - c*40;
            bool ok = kk < K_IN;
            size_t base = (size_t)c*8000 + (size_t)tt*40 + f;
            for (int b = w; b < 128; b += 4) {
                float xv = ok ? __ldg(X + (size_t)b*24000 + base) : 0.0f;
                unsigned short v = (xv > thr) ? (unsigned short)0x3F80
                                 : ((xv < -thr) ? (unsigned short)0xBF80 : (unsigned short)0);
                As[b][lane] = v;
            }
        }
        asm volatile("cp.async.wait_group 0;" ::: "memory");
        __syncthreads();
        if (kc < 3) stageB(kc + 1, (kc + 1) & 1);

        const int buf = kc & 1;
        const unsigned* AsW = (const unsigned*)As;
        #pragma unroll
        for (int e = 0; e < 2; e++) {
            unsigned a[4][4];
            #pragma unroll
            for (int mf = 0; mf < 4; mf++) {
                int row0 = wm*64 + mf*16 + r;
                a[mf][0] = AsW[row0*20       + e*8 + t4];
                a[mf][1] = AsW[(row0 + 8)*20 + e*8 + t4];
                a[mf][2] = AsW[row0*20       + e*8 + t4 + 4];
                a[mf][3] = AsW[(row0 + 8)*20 + e*8 + t4 + 4];
            }
            #pragma unroll
            for (int s = 0; s < 3; s++)
                #pragma unroll
                for (int nf = 0; nf < 4; nf++) {
                    const unsigned* brow = Bs[buf][s][wn*32 + nf*8 + r];
                    unsigned b0 = brow[e*8 + t4];
                    unsigned b1v = brow[e*8 + t4 + 4];
                    #pragma unroll
                    for (int mf = 0; mf < 4; mf++)
                        mma16816(acc[mf][nf], a[mf], b0, b1v);
                }
        }
        __syncthreads();
    }
    #pragma unroll
    for (int nf = 0; nf < 4; nf++) {
        int col = Nb + wn*32 + nf*8 + t4*2;
        float2 bia = *(const float2*)&b1[col];
        #pragma unroll
        for (int mf = 0; mf < 4; mf++) {
            int row = tt*128 + wm*64 + mf*16 + r;
            *(float2*)&g_F[(size_t)row*HID + col] =
                make_float2(acc[mf][nf][0] + bia.x, acc[mf][nf][1] + bia.y);
            *(float2*)&g_F[(size_t)(row + 8)*HID + col] =
                make_float2(acc[mf][nf][2] + bia.x, acc[mf][nf][3] + bia.y);
        }
    }
}

// ---------------- K2: layer-1 LIF scan -> h-linear spike bitmasks -------------
__global__ __launch_bounds__(256)
void k_l1_scan(const float* __restrict__ tau_m1, const float* __restrict__ tau_adp1) {
    int idx = blockIdx.x * 256 + threadIdx.x;    // b*1024 + h
    int h = idx & 1023, b = idx >> 10;
    float alpha = expf(-1.0f / tau_m1[h]);
    float ro    = expf(-1.0f / tau_adp1[h]);
    float mem = 0.0f, spk = 0.0f, bb = 0.01f;
    int word = (h >> 5) & 31;
    int lane = threadIdx.x & 31;
    const float* f = g_F + idx;
    unsigned* mo = g_m1 + (size_t)b*T_STEPS*32 + word;
    for (int t0 = 0; t0 < T_STEPS; t0 += 8) {
        float x[8];
        #pragma unroll
        for (int i = 0; i < 8; i++) x[i] = __ldg(f + (size_t)(t0 + i)*BH);
        #pragma unroll
        for (int i = 0; i < 8; i++) {
            bb = ro*bb + (1.0f - ro)*spk;
            float Bv = 0.01f + 1.8f*bb;
            mem = alpha*mem + (1.0f - alpha)*x[i] - Bv*spk;
            spk = (mem - Bv > 0.0f) ? 1.0f : 0.0f;
            unsigned m = __ballot_sync(0xffffffffu, spk != 0.0f);
            if (lane == 0) mo[(t0 + i)*32] = m;
        }
    }
}

// ---------------- K3: merged dgemm producer + recurrent-step consumer ---------
// grid = 128 step blocks (first) + 3200 dgemm blocks; 128 threads each.
struct StepS {
    unsigned srm[32];
    int cnt[32];
    int off[32];
    int tot, n4;
    unsigned short list[1040];
};
union SmU {
    unsigned dg[2][3][64][20];   // 30720 B dgemm double buffer
    StepS st;
};

__global__ __launch_bounds__(128, 3)
void k_main(const float* __restrict__ tau_m_r, const float* __restrict__ tau_adp_r,
            const float* __restrict__ bd, const float* __restrict__ br) {
    __shared__ __align__(16) SmU sm;
    __shared__ unsigned lut4[4];          // 2 spike bits -> packed bf16 pair
    const int tid = threadIdx.x, lane = tid & 31, w = tid >> 5;

    if (blockIdx.x >= 128) {
        // ================= dgemm role: D(tt) tile (Nb) =================
        const int ds = blockIdx.x - 128;
        const int tt = ds >> 4, Nb = (ds & 15) << 6;
        const int wm = w & 1, wn = w >> 1;
        const int r = lane >> 2, t4 = lane & 3;
        float acc[4][4][4] = {};

        if (tid < 4)
            lut4[tid] = ((tid & 1) ? 0x3F80u : 0u) | ((tid & 2) ? 0x3F800000u : 0u);

        const uint4* wdb4 = (const uint4*)g_WdB;
        const unsigned sb = (unsigned)__cvta_generic_to_shared(sm.dg);

        const unsigned* mp[4][2];
        #pragma unroll
        for (int mf = 0; mf < 4; mf++)
            #pragma unroll
            for (int q = 0; q < 2; q++) {
                int b = wm*64 + mf*16 + r + q*8;
                mp[mf][q] = g_m1 + ((size_t)b*T_STEPS + tt)*32;
            }

        auto stage = [&](int kc, int buf) {
            #pragma unroll
            for (int i = tid; i < 768; i += 128) {
                int s = i >> 8, rem = i & 255, n = rem >> 2, kq = rem & 3;
                unsigned dst = sb + (unsigned)((((buf*3 + s)*64 + n)*20 + kq*4)*4);
                cp16(dst, wdb4 + (size_t)s*131072 + (size_t)(Nb + n)*128 + kc*4 + kq);
            }
            asm volatile("cp.async.commit_group;" ::: "memory");
        };

        stage(0, 0);
        unsigned mk[4][2];
        #pragma unroll
        for (int mf = 0; mf < 4; mf++) {
            mk[mf][0] = __ldg(&mp[mf][0][0]);
            mk[mf][1] = __ldg(&mp[mf][1][0]);
        }

        for (int kc = 0; kc < 32; kc++) {
            asm volatile("cp.async.wait_group 0;" ::: "memory");
            __syncthreads();               // also orders lut4 init before first use
            if (kc < 31) stage(kc + 1, (kc + 1) & 1);

            unsigned mkn[4][2];
            if (kc < 31) {
                #pragma unroll
                for (int mf = 0; mf < 4; mf++) {
                    mkn[mf][0] = __ldg(&mp[mf][0][kc + 1]);
                    mkn[mf][1] = __ldg(&mp[mf][1][kc + 1]);
                }
            }

            const int buf = kc & 1;
            #pragma unroll
            for (int e = 0; e < 2; e++) {
                const int cb = e*16 + t4*2;
                unsigned a[4][4];
                #pragma unroll
                for (int mf = 0; mf < 4; mf++) {
                    a[mf][0] = lut4[(mk[mf][0] >> cb) & 3u];
                    a[mf][1] = lut4[(mk[mf][1] >> cb) & 3u];
                    a[mf][2] = lut4[(mk[mf][0] >> (cb + 8)) & 3u];
                    a[mf][3] = lut4[(mk[mf][1] >> (cb + 8)) & 3u];
                }
                #pragma unroll
                for (int s = 0; s < 3; s++)
                    #pragma unroll
                    for (int nf = 0; nf < 4; nf++) {
                        const unsigned* brow = sm.dg[buf][s][wn*32 + nf*8 + r];
                        unsigned b0 = brow[e*8 + t4];
                        unsigned b1 = brow[e*8 + t4 + 4];
                        #pragma unroll
                        for (int mf = 0; mf < 4; mf++)
                            mma16816(acc[mf][nf], a[mf], b0, b1);
                    }
            }
            #pragma unroll
            for (int mf = 0; mf < 4; mf++) {
                mk[mf][0] = mkn[mf][0];
                mk[mf][1] = mkn[mf][1];
            }
        }
        #pragma unroll
        for (int mf = 0; mf < 4; mf++)
            #pragma unroll
            for (int nf = 0; nf < 4; nf++) {
                int col = Nb + wn*32 + nf*8 + t4*2;
                int row = tt*128 + wm*64 + mf*16 + r;
                *(float2*)&g_F[(size_t)row*HID + col] =
                    make_float2(acc[mf][nf][0], acc[mf][nf][1]);
                *(float2*)&g_F[(size_t)(row + 8)*HID + col] =
                    make_float2(acc[mf][nf][2], acc[mf][nf][3]);
            }
        __threadfence();                 // each thread releases its stores
        __syncthreads();
        if (tid == 0) atomicAdd(&g_done[tt], 1);
        return;
    }

    // ================= step role: one batch sample, 8 neurons/thread ==========
    const int b = blockIdx.x;
    const int j0 = tid * 8;

    float al[8], ro[8], bi[8], mem[8], bb[8], sp[8];
    #pragma unroll
    for (int i = 0; i < 8; i++) {
        al[i] = expf(-1.0f / tau_m_r[j0 + i]);
        ro[i] = expf(-1.0f / tau_adp_r[j0 + i]);
        bi[i] = bd[j0 + i] + br[j0 + i];
        mem[i] = 0.0f; bb[i] = 0.01f; sp[i] = 0.0f;
    }
    if (tid < 32) sm.st.srm[tid] = 0u;
    __syncthreads();

    const float4* wp = (const float4*)(g_WrT + j0);      // 2 float4 per row
    const float4* fbase = (const float4*)(g_F + (size_t)b*HID + j0);
    unsigned* mout = g_masks + (size_t)b*T_STEPS*32;
    volatile int* done = g_done;

    for (int t = 0; t < T_STEPS; t++) {
        // 0. wait for D(t) tiles from dgemm role (backoff poll)
        if (tid == 0) {
            while (done[t] < 16) { __nanosleep(64); }
        }
        __syncthreads();
        // issue F(t) loads early: latency overlaps compaction below
        float4 fa = ldcg4(fbase + (size_t)t*(BH/4));
        float4 fb = ldcg4(fbase + (size_t)t*(BH/4) + 1);
        // 1. counts of active sr words
        unsigned myw = (tid < 32) ? sm.st.srm[tid] : 0u;
        if (tid < 32) sm.st.cnt[tid] = __popc(myw);
        __syncthreads();
        // 2. exclusive scan (warp 0)
        if (tid < 32) {
            int c = sm.st.cnt[tid];
            int inc = c;
            #pragma unroll
            for (int d = 1; d < 32; d <<= 1) {
                int v = __shfl_up_sync(0xffffffffu, inc, d);
                if (lane >= d) inc += v;
            }
            sm.st.off[tid] = inc - c;
            if (tid == 31) { sm.st.tot = inc; sm.st.n4 = (inc + 3) & ~3; }
        }
        __syncthreads();
        // 3. expand ballots (word v: h = (v>>3)*256 + l*8 + (v&7))
        if (tid < 32) {
            int o = sm.st.off[tid];
            unsigned m = myw;
            int base = (tid >> 3)*256 + (tid & 7);
            while (m) {
                int l = __ffs(m) - 1; m &= m - 1;
                sm.st.list[o++] = (unsigned short)(base + l*8);
            }
        }
        for (int i = sm.st.tot + tid; i < sm.st.n4; i += 128)
            sm.st.list[i] = (unsigned short)1024;
        __syncthreads();
        // 4. fp32 gather over active rows
        const int n4 = sm.st.n4;
        float a0 = fa.x + bi[0], a1 = fa.y + bi[1], a2 = fa.z + bi[2], a3 = fa.w + bi[3];
        float a4 = fb.x + bi[4], a5 = fb.y + bi[5], a6 = fb.z + bi[6], a7 = fb.w + bi[7];
        for (int i = 0; i < n4; i += 4) {
            uint2 u = *(const uint2*)&sm.st.list[i];
            int e0 = u.x & 0xffff, e1 = u.x >> 16;
            int e2 = u.y & 0xffff, e3 = u.y >> 16;
            float4 v0a = __ldg(wp + (size_t)e0*(HID/4)), v0b = __ldg(wp + (size_t)e0*(HID/4) + 1);
            float4 v1a = __ldg(wp + (size_t)e1*(HID/4)), v1b = __ldg(wp + (size_t)e1*(HID/4) + 1);
            float4 v2a = __ldg(wp + (size_t)e2*(HID/4)), v2b = __ldg(wp + (size_t)e2*(HID/4) + 1);
            float4 v3a = __ldg(wp + (size_t)e3*(HID/4)), v3b = __ldg(wp + (size_t)e3*(HID/4) + 1);
            a0 += (v0a.x + v1a.x) + (v2a.x + v3a.x);
            a1 += (v0a.y + v1a.y) + (v2a.y + v3a.y);
            a2 += (v0a.z + v1a.z) + (v2a.z + v3a.z);
            a3 += (v0a.w + v1a.w) + (v2a.w + v3a.w);
            a4 += (v0b.x + v1b.x) + (v2b.x + v3b.x);
            a5 += (v0b.y + v1b.y) + (v2b.y + v3b.y);
            a6 += (v0b.z + v1b.z) + (v2b.z + v3b.z);
            a7 += (v0b.w + v1b.w) + (v2b.w + v3b.w);
        }
        float x[8] = {a0, a1, a2, a3, a4, a5, a6, a7};
        // 5. adaptive LIF update (8 neurons)
        #pragma unroll
        for (int i = 0; i < 8; i++) {
            bb[i] = ro[i]*bb[i] + (1.0f - ro[i])*sp[i];
            float Bv = 0.01f + 1.8f*bb[i];
            mem[i] = al[i]*mem[i] + (1.0f - al[i])*x[i] - Bv*sp[i];
            sp[i] = (mem[i] - Bv > 0.0f) ? 1.0f : 0.0f;
        }
        __syncthreads();                  // list fully consumed before overwrite
        // 6. ballots -> smem (next step) + global (readout)
        #pragma unroll
        for (int i = 0; i < 8; i++) {
            unsigned m = __ballot_sync(0xffffffffu, sp[i] != 0.0f);
            if (lane == 0) {
                sm.st.srm[w*8 + i] = m;
                mout[t*32 + w*8 + i] = m;
            }
        }
        __syncthreads();
    }
}

// ---------------- K4: readout + log_softmax -----------------------------------
__global__ __launch_bounds__(256)
void k_readout(const float* __restrict__ b2, float* __restrict__ out) {
    __shared__ float red[256][NOUT];
    __shared__ float vals[NOUT];
    __shared__ float s_l;
    const int b = blockIdx.x, tid = threadIdx.x;
    float acc[NOUT] = {};
    if (tid < T_STEPS) {
        float sum[NOUT] = {};
        const unsigned* gm = g_masks + ((size_t)b*T_STEPS + tid)*32;
        for (int v = 0; v < 32; v++) {
            unsigned m = gm[v];
            int base = (v >> 3)*256 + (v & 7);
            while (m) {
                int l = __ffs(m) - 1; m &= m - 1;
                const float* w2 = &g_W2T[(base + l*8)*NOUT];
                #pragma unroll
                for (int o = 0; o < NOUT; o++) sum[o] += w2[o];
            }
        }
        const float* c = &g_ctab[tid*NOUT];
        #pragma unroll
        for (int o = 0; o < NOUT; o++) acc[o] = c[o]*sum[o];
    }
    #pragma unroll
    for (int o = 0; o < NOUT; o++) red[tid][o] = acc[o];
    __syncthreads();
    for (int s = 128; s > 0; s >>= 1) {
        if (tid < s)
            #pragma unroll
            for (int o = 0; o < NOUT; o++) red[tid][o] += red[tid + s][o];
        __syncthreads();
    }
    if (tid < NOUT)
        vals[tid] = (red[0][tid] + g_csum[tid]*b2[tid]) * (1.0f / (float)T_STEPS);
    __syncthreads();
    if (tid == 0) {
        float m = vals[0];
        for (int o = 1; o < NOUT; o++) m = fmaxf(m, vals[o]);
        float s = 0.0f;
        for (int o = 0; o < NOUT; o++) s += expf(vals[o] - m);
        s_l = m + logf(s);
    }
    __syncthreads();
    if (tid < NOUT) out[b*NOUT + tid] = vals[tid] - s_l;
}

// ---------------- launch -------------------------------------------------------
extern "C" void kernel_launch(void* const* d_in, const int* in_sizes, int n_in,
                              void* d_out, int out_size) {
    const float* X        = (const float*)d_in[0];
    const float* thr      = (const float*)d_in[1];
    const float* W1       = (const float*)d_in[2];
    const float* b1       = (const float*)d_in[3];
    const float* Wd       = (const float*)d_in[4];
    const float* bd       = (const float*)d_in[5];
    const float* Wr       = (const float*)d_in[6];
    const float* br       = (const float*)d_in[7];
    const float* W2       = (const float*)d_in[8];
    const float* b2       = (const float*)d_in[9];
    const float* tau_m1   = (const float*)d_in[10];
    const float* tau_adp1 = (const float*)d_in[11];
    const float* tau_m_r  = (const float*)d_in[12];
    const float* tau_adp_r= (const float*)d_in[13];
    const float* tau_m2   = (const float*)d_in[14];
    float* out = (float*)d_out;

    k_prep<<<(HID*HID + 255)/256, 256>>>(Wd, Wr, W1, W2, tau_m2);
    k_in_mma<<<dim3(T_STEPS, 16), 128>>>(X, thr, b1);
    k_l1_scan<<<BH/256, 256>>>(tau_m1, tau_adp1);
    k_main<<<128 + T_STEPS*16, 128>>>(tau_m_r, tau_adp_r, bd, br);
    k_readout<<<BATCH, 256>>>(b2, out);
}

// round 15
// speedup vs baseline: 1.0191x; 1.0191x over previous
#include <cuda_runtime.h>
#include <cuda_bf16.h>
#include <math.h>

#define T_STEPS 200
#define BATCH   128
#define HID     1024
#define K_IN    120
#define NOUT    12
#define BH      (BATCH*HID)      // 131072
#define NROWS   (T_STEPS*BATCH)  // 25600

// ---------------- static device scratch (no allocations allowed) ------------
__device__ float          g_F[NROWS*HID];       // W1 drive, then overwritten by D = S1@Wd^T
__device__ float          g_WrT[1025*HID];      // Wr^T fp32 [h][j] + zero pad row
__device__ __nv_bfloat16  g_WdB[3][HID*HID];    // Wd 3-way bf16 split, [j][h] native layout
__device__ __nv_bfloat16  g_W1B[3][HID*128];    // W1 3-way bf16 split, [n][k] padded 120->128
__device__ float          g_W2T[HID*NOUT];
__device__ unsigned       g_m1[(size_t)BATCH*T_STEPS*32];    // layer-1 spike masks (h-linear)
__device__ unsigned       g_masks[(size_t)BATCH*T_STEPS*32]; // recurrent spike ballots
__device__ float          g_ctab[T_STEPS*NOUT];
__device__ float          g_csum[NOUT];
__device__ int            g_done[T_STEPS];      // dgemm tile-completion counters

// ---------------- prep A: coalesced smem-tiled Wr transpose -------------------
__global__ __launch_bounds__(256)
void k_prep_t(const float* __restrict__ Wr) {
    __shared__ float tile[32][33];
    const int jt = blockIdx.x * 32, ht = blockIdx.y * 32;
    const int tx = threadIdx.x & 31, ty = threadIdx.x >> 5;   // 32 x 8
    #pragma unroll
    for (int i = 0; i < 32; i += 8)
        tile[ty + i][tx] = Wr[(size_t)(jt + ty + i)*HID + ht + tx];
    __syncthreads();
    #pragma unroll
    for (int i = 0; i < 32; i += 8)
        g_WrT[(size_t)(ht + ty + i)*HID + jt + tx] = tile[tx][ty + i];
}

// ---------------- prep B: Wd/W1 3-split, W2T, tables, flags, pad row ----------
__global__ __launch_bounds__(256)
void k_prep(const float* __restrict__ Wd, const float* __restrict__ W1,
            const float* __restrict__ W2, const float* __restrict__ tau_m2) {
    int idx = blockIdx.x * 256 + threadIdx.x;
    if (idx < HID*HID) {
        float w = Wd[idx];
        __nv_bfloat16 h1 = __float2bfloat16(w);
        float r1 = w - __bfloat162float(h1);
        __nv_bfloat16 h2 = __float2bfloat16(r1);
        float r2 = r1 - __bfloat162float(h2);
        __nv_bfloat16 h3 = __float2bfloat16(r2);
        g_WdB[0][idx] = h1;
        g_WdB[1][idx] = h2;
        g_WdB[2][idx] = h3;
    }
    if (idx < HID*128) {                         // W1 split, K padded to 128
        int n = idx >> 7, k = idx & 127;
        float w = (k < K_IN) ? W1[n*K_IN + k] : 0.0f;
        __nv_bfloat16 h1 = __float2bfloat16(w);
        float r1 = w - __bfloat162float(h1);
        __nv_bfloat16 h2 = __float2bfloat16(r1);
        float r2 = r1 - __bfloat162float(h2);
        __nv_bfloat16 h3 = __float2bfloat16(r2);
        g_W1B[0][idx] = h1;
        g_W1B[1][idx] = h2;
        g_W1B[2][idx] = h3;
    }
    if (idx < HID*NOUT) {
        int h = idx / NOUT, o = idx % NOUT;
        g_W2T[idx] = W2[o*HID + h];
    }
    if (idx < T_STEPS*NOUT) {
        int k = idx / NOUT, o = idx % NOUT;
        float a2 = expf(-1.0f / tau_m2[o]);
        g_ctab[idx] = 1.0f - powf(a2, (float)(T_STEPS - k));
    }
    if (idx < NOUT) {
        float a2 = expf(-1.0f / tau_m2[idx]);
        float s = 0.0f, p = 1.0f;
        for (int n = 1; n <= T_STEPS; n++) { p *= a2; s += p; }
        g_csum[idx] = (float)T_STEPS - s;
    }
    if (idx < HID) g_WrT[(size_t)1024*HID + idx] = 0.0f;   // zero pad row
    if (idx < T_STEPS) g_done[idx] = 0;                    // reset every launch
}

// ---------------- shared mma helpers ------------------------------------------
__device__ __forceinline__ void mma16816(float* c, const unsigned* a, unsigned b0, unsigned b1) {
    asm volatile("mma.sync.aligned.m16n8k16.row.col.f32.bf16.bf16.f32 "
        "{%0,%1,%2,%3}, {%4,%5,%6,%7}, {%8,%9}, {%0,%1,%2,%3};"
        : "+f"(c[0]), "+f"(c[1]), "+f"(c[2]), "+f"(c[3])
        : "r"(a[0]), "r"(a[1]), "r"(a[2]), "r"(a[3]), "r"(b0), "r"(b1));
}
__device__ __forceinline__ unsigned spike_pack(unsigned m, int c) {
    return (((m >> c) & 1u) ? 0x3F80u : 0u) | (((m >> (c+1)) & 1u) ? 0x3F800000u : 0u);
}
__device__ __forceinline__ void cp16(unsigned dst, const void* src) {
    asm volatile("cp.async.cg.shared.global [%0], [%1], 16;" :: "r"(dst), "l"(src) : "memory");
}
__device__ __forceinline__ float4 ldcg4(const float4* p) {
    float4 v;
    asm volatile("ld.global.cg.v4.f32 {%0,%1,%2,%3}, [%4];"
        : "=f"(v.x), "=f"(v.y), "=f"(v.z), "=f"(v.w) : "l"(p));
    return v;
}

// ---------------- K1: F = ternary(X) @ W1^T + b1 via mma (bf16 3-split) -------
__global__ __launch_bounds__(128, 3)
void k_in_mma(const float* __restrict__ X, const float* __restrict__ thrp,
              const float* __restrict__ b1) {
    __shared__ unsigned short As[128][40];
    __shared__ unsigned Bs[2][3][64][20];
    const int tid = threadIdx.x, lane = tid & 31, w = tid >> 5;
    const int wm = w & 1, wn = w >> 1;
    const int tt = blockIdx.x, Nb = blockIdx.y * 64;
    const int r = lane >> 2, t4 = lane & 3;
    const float thr = __ldg(thrp);
    float acc[4][4][4] = {};

    const uint4* w1b4 = (const uint4*)g_W1B;
    const unsigned sbB = (unsigned)__cvta_generic_to_shared(Bs);

    auto stageB = [&](int kc, int buf) {
        #pragma unroll
        for (int i = tid; i < 768; i += 128) {
            int s = i >> 8, rem = i & 255, n = rem >> 2, kq = rem & 3;
            unsigned dst = sbB + (unsigned)((((buf*3 + s)*64 + n)*20 + kq*4)*4);
            cp16(dst, w1b4 + (size_t)s*16384 + (size_t)(Nb + n)*16 + kc*4 + kq);
        }
        asm volatile("cp.async.commit_group;" ::: "memory");
    };
    stageB(0, 0);

    for (int kc = 0; kc < 4; kc++) {
        {
            int kk = kc*32 + lane;
            int c = kk / 40, f = kk - c*40;
            bool ok = kk < K_IN;
            size_t base = (size_t)c*8000 + (size_t)tt*40 + f;
            for (int b = w; b < 128; b += 4) {
                float xv = ok ? __ldg(X + (size_t)b*24000 + base) : 0.0f;
                unsigned short v = (xv > thr) ? (unsigned short)0x3F80
                                 : ((xv < -thr) ? (unsigned short)0xBF80 : (unsigned short)0);
                As[b][lane] = v;
            }
        }
        asm volatile("cp.async.wait_group 0;" ::: "memory");
        __syncthreads();
        if (kc < 3) stageB(kc + 1, (kc + 1) & 1);

        const int buf = kc & 1;
        const unsigned* AsW = (const unsigned*)As;
        #pragma unroll
        for (int e = 0; e < 2; e++) {
            unsigned a[4][4];
            #pragma unroll
            for (int mf = 0; mf < 4; mf++) {
                int row0 = wm*64 + mf*16 + r;
                a[mf][0] = AsW[row0*20       + e*8 + t4];
                a[mf][1] = AsW[(row0 + 8)*20 + e*8 + t4];
                a[mf][2] = AsW[row0*20       + e*8 + t4 + 4];
                a[mf][3] = AsW[(row0 + 8)*20 + e*8 + t4 + 4];
            }
            #pragma unroll
            for (int s = 0; s < 3; s++)
                #pragma unroll
                for (int nf = 0; nf < 4; nf++) {
                    const unsigned* brow = Bs[buf][s][wn*32 + nf*8 + r];
                    unsigned b0 = brow[e*8 + t4];
                    unsigned b1v = brow[e*8 + t4 + 4];
                    #pragma unroll
                    for (int mf = 0; mf < 4; mf++)
                        mma16816(acc[mf][nf], a[mf], b0, b1v);
                }
        }
        __syncthreads();
    }
    #pragma unroll
    for (int nf = 0; nf < 4; nf++) {
        int col = Nb + wn*32 + nf*8 + t4*2;
        float2 bia = *(const float2*)&b1[col];
        #pragma unroll
        for (int mf = 0; mf < 4; mf++) {
            int row = tt*128 + wm*64 + mf*16 + r;
            *(float2*)&g_F[(size_t)row*HID + col] =
                make_float2(acc[mf][nf][0] + bia.x, acc[mf][nf][1] + bia.y);
            *(float2*)&g_F[(size_t)(row + 8)*HID + col] =
                make_float2(acc[mf][nf][2] + bia.x, acc[mf][nf][3] + bia.y);
        }
    }
}

// ---------------- K2: layer-1 LIF scan -> h-linear spike bitmasks -------------
__global__ __launch_bounds__(256)
void k_l1_scan(const float* __restrict__ tau_m1, const float* __restrict__ tau_adp1) {
    int idx = blockIdx.x * 256 + threadIdx.x;    // b*1024 + h
    int h = idx & 1023, b = idx >> 10;
    float alpha = expf(-1.0f / tau_m1[h]);
    float ro    = expf(-1.0f / tau_adp1[h]);
    float mem = 0.0f, spk = 0.0f, bb = 0.01f;
    int word = (h >> 5) & 31;
    int lane = threadIdx.x & 31;
    const float* f = g_F + idx;
    unsigned* mo = g_m1 + (size_t)b*T_STEPS*32 + word;
    for (int t0 = 0; t0 < T_STEPS; t0 += 8) {
        float x[8];
        #pragma unroll
        for (int i = 0; i < 8; i++) x[i] = __ldg(f + (size_t)(t0 + i)*BH);
        #pragma unroll
        for (int i = 0; i < 8; i++) {
            bb = ro*bb + (1.0f - ro)*spk;
            float Bv = 0.01f + 1.8f*bb;
            mem = alpha*mem + (1.0f - alpha)*x[i] - Bv*spk;
            spk = (mem - Bv > 0.0f) ? 1.0f : 0.0f;
            unsigned m = __ballot_sync(0xffffffffu, spk != 0.0f);
            if (lane == 0) mo[(t0 + i)*32] = m;
        }
    }
}

// ---------------- K3: merged dgemm producer + recurrent-step consumer ---------
// grid = 128 step blocks (first) + 3200 dgemm blocks; 128 threads each.
struct StepS {
    unsigned srm[32];
    int cnt[32];
    int off[32];
    int tot, n4;
    unsigned short list[1040];
};
union SmU {
    unsigned dg[2][3][64][20];   // 30720 B dgemm double buffer
    StepS st;
};

__global__ __launch_bounds__(128, 3)
void k_main(const float* __restrict__ tau_m_r, const float* __restrict__ tau_adp_r,
            const float* __restrict__ bd, const float* __restrict__ br) {
    __shared__ __align__(16) SmU sm;
    const int tid = threadIdx.x, lane = tid & 31, w = tid >> 5;

    if (blockIdx.x >= 128) {
        // ================= dgemm role: D(tt) tile (Nb) =================
        const int ds = blockIdx.x - 128;
        const int tt = ds >> 4, Nb = (ds & 15) << 6;
        const int wm = w & 1, wn = w >> 1;
        const int r = lane >> 2, t4 = lane & 3;
        float acc[4][4][4] = {};

        const uint4* wdb4 = (const uint4*)g_WdB;
        const unsigned sb = (unsigned)__cvta_generic_to_shared(sm.dg);

        const unsigned* mp[4][2];
        #pragma unroll
        for (int mf = 0; mf < 4; mf++)
            #pragma unroll
            for (int q = 0; q < 2; q++) {
                int b = wm*64 + mf*16 + r + q*8;
                mp[mf][q] = g_m1 + ((size_t)b*T_STEPS + tt)*32;
            }

        auto stage = [&](int kc, int buf) {
            #pragma unroll
            for (int i = tid; i < 768; i += 128) {
                int s = i >> 8, rem = i & 255, n = rem >> 2, kq = rem & 3;
                unsigned dst = sb + (unsigned)((((buf*3 + s)*64 + n)*20 + kq*4)*4);
                cp16(dst, wdb4 + (size_t)s*131072 + (size_t)(Nb + n)*128 + kc*4 + kq);
            }
            asm volatile("cp.async.commit_group;" ::: "memory");
        };

        stage(0, 0);
        unsigned mk[4][2];
        #pragma unroll
        for (int mf = 0; mf < 4; mf++) {
            mk[mf][0] = __ldg(&mp[mf][0][0]);
            mk[mf][1] = __ldg(&mp[mf][1][0]);
        }

        for (int kc = 0; kc < 32; kc++) {
            asm volatile("cp.async.wait_group 0;" ::: "memory");
            __syncthreads();
            if (kc < 31) stage(kc + 1, (kc + 1) & 1);

            unsigned mkn[4][2];
            if (kc < 31) {
                #pragma unroll
                for (int mf = 0; mf < 4; mf++) {
                    mkn[mf][0] = __ldg(&mp[mf][0][kc + 1]);
                    mkn[mf][1] = __ldg(&mp[mf][1][kc + 1]);
                }
            }

            const int buf = kc & 1;
            #pragma unroll
            for (int e = 0; e < 2; e++) {
                const int cb = e*16 + t4*2;
                unsigned a[4][4];
                #pragma unroll
                for (int mf = 0; mf < 4; mf++) {
                    a[mf][0] = spike_pack(mk[mf][0], cb);
                    a[mf][1] = spike_pack(mk[mf][1], cb);
                    a[mf][2] = spike_pack(mk[mf][0], cb + 8);
                    a[mf][3] = spike_pack(mk[mf][1], cb + 8);
                }
                #pragma unroll
                for (int s = 0; s < 3; s++)
                    #pragma unroll
                    for (int nf = 0; nf < 4; nf++) {
                        const unsigned* brow = sm.dg[buf][s][wn*32 + nf*8 + r];
                        unsigned b0 = brow[e*8 + t4];
                        unsigned b1 = brow[e*8 + t4 + 4];
                        #pragma unroll
                        for (int mf = 0; mf < 4; mf++)
                            mma16816(acc[mf][nf], a[mf], b0, b1);
                    }
            }
            #pragma unroll
            for (int mf = 0; mf < 4; mf++) {
                mk[mf][0] = mkn[mf][0];
                mk[mf][1] = mkn[mf][1];
            }
        }
        #pragma unroll
        for (int mf = 0; mf < 4; mf++)
            #pragma unroll
            for (int nf = 0; nf < 4; nf++) {
                int col = Nb + wn*32 + nf*8 + t4*2;
                int row = tt*128 + wm*64 + mf*16 + r;
                *(float2*)&g_F[(size_t)row*HID + col] =
                    make_float2(acc[mf][nf][0], acc[mf][nf][1]);
                *(float2*)&g_F[(size_t)(row + 8)*HID + col] =
                    make_float2(acc[mf][nf][2], acc[mf][nf][3]);
            }
        __threadfence();                 // each thread releases its stores
        __syncthreads();
        if (tid == 0) atomicAdd(&g_done[tt], 1);
        return;
    }

    // ================= step role: one batch sample, 8 neurons/thread ==========
    const int b = blockIdx.x;
    const int j0 = tid * 8;

    float al[8], ro[8], bi[8], mem[8], bb[8], sp[8];
    #pragma unroll
    for (int i = 0; i < 8; i++) {
        al[i] = expf(-1.0f / tau_m_r[j0 + i]);
        ro[i] = expf(-1.0f / tau_adp_r[j0 + i]);
        bi[i] = bd[j0 + i] + br[j0 + i];
        mem[i] = 0.0f; bb[i] = 0.01f; sp[i] = 0.0f;
    }
    if (tid < 32) sm.st.srm[tid] = 0u;
    __syncthreads();

    const float4* wp = (const float4*)(g_WrT + j0);      // 2 float4 per row
    const float4* fbase = (const float4*)(g_F + (size_t)b*HID + j0);
    unsigned* mout = g_masks + (size_t)b*T_STEPS*32;
    volatile int* done = g_done;

    for (int t = 0; t < T_STEPS; t++) {
        // 0. wait for D(t) tiles from dgemm role (backoff poll)
        if (tid == 0) {
            while (done[t] < 16) { __nanosleep(64); }
        }
        __syncthreads();
        // issue F(t) loads early: latency overlaps compaction below
        float4 fa = ldcg4(fbase + (size_t)t*(BH/4));
        float4 fb = ldcg4(fbase + (size_t)t*(BH/4) + 1);
        // 1. counts of active sr words
        unsigned myw = (tid < 32) ? sm.st.srm[tid] : 0u;
        if (tid < 32) sm.st.cnt[tid] = __popc(myw);
        __syncthreads();
        // 2. exclusive scan (warp 0)
        if (tid < 32) {
            int c = sm.st.cnt[tid];
            int inc = c;
            #pragma unroll
            for (int d = 1; d < 32; d <<= 1) {
                int v = __shfl_up_sync(0xffffffffu, inc, d);
                if (lane >= d) inc += v;
            }
            sm.st.off[tid] = inc - c;
            if (tid == 31) { sm.st.tot = inc; sm.st.n4 = (inc + 3) & ~3; }
        }
        __syncthreads();
        // 3. expand ballots (word v: h = (v>>3)*256 + l*8 + (v&7))
        if (tid < 32) {
            int o = sm.st.off[tid];
            unsigned m = myw;
            int base = (tid >> 3)*256 + (tid & 7);
            while (m) {
                int l = __ffs(m) - 1; m &= m - 1;
                sm.st.list[o++] = (unsigned short)(base + l*8);
            }
        }
        for (int i = sm.st.tot + tid; i < sm.st.n4; i += 128)
            sm.st.list[i] = (unsigned short)1024;
        __syncthreads();
        // 4. fp32 gather over active rows
        const int n4 = sm.st.n4;
        float a0 = fa.x + bi[0], a1 = fa.y + bi[1], a2 = fa.z + bi[2], a3 = fa.w + bi[3];
        float a4 = fb.x + bi[4], a5 = fb.y + bi[5], a6 = fb.z + bi[6], a7 = fb.w + bi[7];
        for (int i = 0; i < n4; i += 4) {
            uint2 u = *(const uint2*)&sm.st.list[i];
            int e0 = u.x & 0xffff, e1 = u.x >> 16;
            int e2 = u.y & 0xffff, e3 = u.y >> 16;
            float4 v0a = __ldg(wp + (size_t)e0*(HID/4)), v0b = __ldg(wp + (size_t)e0*(HID/4) + 1);
            float4 v1a = __ldg(wp + (size_t)e1*(HID/4)), v1b = __ldg(wp + (size_t)e1*(HID/4) + 1);
            float4 v2a = __ldg(wp + (size_t)e2*(HID/4)), v2b = __ldg(wp + (size_t)e2*(HID/4) + 1);
            float4 v3a = __ldg(wp + (size_t)e3*(HID/4)), v3b = __ldg(wp + (size_t)e3*(HID/4) + 1);
            a0 += (v0a.x + v1a.x) + (v2a.x + v3a.x);
            a1 += (v0a.y + v1a.y) + (v2a.y + v3a.y);
            a2 += (v0a.z + v1a.z) + (v2a.z + v3a.z);
            a3 += (v0a.w + v1a.w) + (v2a.w + v3a.w);
            a4 += (v0b.x + v1b.x) + (v2b.x + v3b.x);
            a5 += (v0b.y + v1b.y) + (v2b.y + v3b.y);
            a6 += (v0b.z + v1b.z) + (v2b.z + v3b.z);
            a7 += (v0b.w + v1b.w) + (v2b.w + v3b.w);
        }
        float x[8] = {a0, a1, a2, a3, a4, a5, a6, a7};
        // 5. adaptive LIF update (8 neurons)
        #pragma unroll
        for (int i = 0; i < 8; i++) {
            bb[i] = ro[i]*bb[i] + (1.0f - ro[i])*sp[i];
            float Bv = 0.01f + 1.8f*bb[i];
            mem[i] = al[i]*mem[i] + (1.0f - al[i])*x[i] - Bv*sp[i];
            sp[i] = (mem[i] - Bv > 0.0f) ? 1.0f : 0.0f;
        }
        __syncthreads();                  // list fully consumed before overwrite
        // 6. ballots -> smem (next step) + global (readout)
        #pragma unroll
        for (int i = 0; i < 8; i++) {
            unsigned m = __ballot_sync(0xffffffffu, sp[i] != 0.0f);
            if (lane == 0) {
                sm.st.srm[w*8 + i] = m;
                mout[t*32 + w*8 + i] = m;
            }
        }
        __syncthreads();
    }
}

// ---------------- K4: readout + log_softmax -----------------------------------
__global__ __launch_bounds__(256)
void k_readout(const float* __restrict__ b2, float* __restrict__ out) {
    __shared__ float red[256][NOUT];
    __shared__ float vals[NOUT];
    __shared__ float s_l;
    const int b = blockIdx.x, tid = threadIdx.x;
    float acc[NOUT] = {};
    if (tid < T_STEPS) {
        float sum[NOUT] = {};
        const unsigned* gm = g_masks + ((size_t)b*T_STEPS + tid)*32;
        for (int v = 0; v < 32; v++) {
            unsigned m = gm[v];
            int base = (v >> 3)*256 + (v & 7);
            while (m) {
                int l = __ffs(m) - 1; m &= m - 1;
                const float* w2 = &g_W2T[(base + l*8)*NOUT];
                #pragma unroll
                for (int o = 0; o < NOUT; o++) sum[o] += w2[o];
            }
        }
        const float* c = &g_ctab[tid*NOUT];
        #pragma unroll
        for (int o = 0; o < NOUT; o++) acc[o] = c[o]*sum[o];
    }
    #pragma unroll
    for (int o = 0; o < NOUT; o++) red[tid][o] = acc[o];
    __syncthreads();
    for (int s = 128; s > 0; s >>= 1) {
        if (tid < s)
            #pragma unroll
            for (int o = 0; o < NOUT; o++) red[tid][o] += red[tid + s][o];
        __syncthreads();
    }
    if (tid < NOUT)
        vals[tid] = (red[0][tid] + g_csum[tid]*b2[tid]) * (1.0f / (float)T_STEPS);
    __syncthreads();
    if (tid == 0) {
        float m = vals[0];
        for (int o = 1; o < NOUT; o++) m = fmaxf(m, vals[o]);
        float s = 0.0f;
        for (int o = 0; o < NOUT; o++) s += expf(vals[o] - m);
        s_l = m + logf(s);
    }
    __syncthreads();
    if (tid < NOUT) out[b*NOUT + tid] = vals[tid] - s_l;
}

// ---------------- launch -------------------------------------------------------
extern "C" void kernel_launch(void* const* d_in, const int* in_sizes, int n_in,
                              void* d_out, int out_size) {
    const float* X        = (const float*)d_in[0];
    const float* thr      = (const float*)d_in[1];
    const float* W1       = (const float*)d_in[2];
    const float* b1       = (const float*)d_in[3];
    const float* Wd       = (const float*)d_in[4];
    const float* bd       = (const float*)d_in[5];
    const float* Wr       = (const float*)d_in[6];
    const float* br       = (const float*)d_in[7];
    const float* W2       = (const float*)d_in[8];
    const float* b2       = (const float*)d_in[9];
    const float* tau_m1   = (const float*)d_in[10];
    const float* tau_adp1 = (const float*)d_in[11];
    const float* tau_m_r  = (const float*)d_in[12];
    const float* tau_adp_r= (const float*)d_in[13];
    const float* tau_m2   = (const float*)d_in[14];
    float* out = (float*)d_out;

    k_prep_t<<<dim3(32, 32), 256>>>(Wr);
    k_prep<<<(HID*HID + 255)/256, 256>>>(Wd, W1, W2, tau_m2);
    k_in_mma<<<dim3(T_STEPS, 16), 128>>>(X, thr, b1);
    k_l1_scan<<<BH/256, 256>>>(tau_m1, tau_adp1);
    k_main<<<128 + T_STEPS*16, 128>>>(tau_m_r, tau_adp_r, bd, br);
    k_readout<<<BATCH, 256>>>(b2, out);
}